// round 7
// baseline (speedup 1.0000x reference)
#include <cuda_runtime.h>

#define Wd 384
#define Hd 256
#define HWD (Wd*Hd)

// Output: (N=2, A2=49, C=3, H, W) fp32
// Input0: low_rank (N, L=3, R=4, C=3, H, W) fp32 ; Input1: planes (N, L)
//
// Identity grid + constant per-(n,l,view) shift; taps/weights pixel-independent;
// borders via clamped load addresses. Lane owns pixels (x, x+1); neighbor column
// interps via __shfl (3x load dedup); lanes 0/31 fetch clamped halo pairs.
// Lean version: 32-bit offsets, lazy edge loads, precomputed weights, fused l2.

__global__ __launch_bounds__(256, 3)
void lfs2_kernel(const float* __restrict__ lr,
                 const float* __restrict__ planes,
                 float* __restrict__ out)
{
    const int lane = threadIdx.x;
    const int XB = blockIdx.x * 64;
    const int x  = XB + lane * 2;
    const int y  = blockIdx.y * 8 + threadIdx.y;
    const int z  = blockIdx.z;                 // n*21 + kq*3 + c
    const int n  = z / 21;
    const int zc = z - n * 21;
    const int kq = zc / 3;
    const int c  = zc - kq * 3;

    const float cy = 255.0f / 512.0f;
    const float cx = 383.0f / 768.0f;

    const bool isL = (lane == 0), isR = (lane == 31);
    const bool edge = isL || isR;
    // clamped halo columns (only meaningful for lanes 0/31)
    int h0 = isR ? min(x + 2, Wd - 1) : max(x - 2, 0);
    int h1 = isR ? min(x + 3, Wd - 1) : max(x - 1, 0);

    const float* basec = lr + (size_t)(n * 36 + c) * HWD;  // + l*12*HWD + r*3*HWD + row
    const float* px0   = basec + x;

    float wy_l[3];
    int lo_l[3], hi_l[3];          // l*12*HWD + row0/row1 offsets
    float u0[3], u1[3], u2[3], u4[3], u5[3], u6[3];
    bool armB[3];
#pragma unroll
    for (int l = 0; l < 3; l++) {
        float p   = __ldg(planes + n * 3 + l);
        float dyv = p * cy * (float)(3 - kq);
        float fy  = floorf(dyv);
        wy_l[l]   = dyv - fy;
        int iy0   = y + (int)fy;
        lo_l[l] = l * (12 * HWD) + min(max(iy0,     0), Hd - 1) * Wd;
        hi_l[l] = l * (12 * HWD) + min(max(iy0 + 1, 0), Hd - 1) * Wd;
        float s = p * cx;
        bool b  = (3.0f * s > 1.0f);
        armB[l] = b;
        u0[l] = b ? (3.f*s - 1.f) : (3.f*s);
        u1[l] = 2.f*s;
        u2[l] = s;
        u4[l] = 1.f - s;
        u5[l] = 1.f - 2.f*s;
        u6[l] = b ? (2.f - 3.f*s) : (1.f - 3.f*s);
    }

    float sum0[7], sum1[7];
#pragma unroll
    for (int i = 0; i < 7; i++) { sum0[i] = 0.0f; sum1[i] = 0.0f; }

    int roff = 0;
#pragma unroll 1
    for (int r = 0; r < 4; r++, roff += 3 * HWD) {
        float p0[7], p1[7];

#pragma unroll
        for (int l = 0; l < 3; l++) {
            const int o0 = roff + lo_l[l];
            const int o1 = roff + hi_l[l];
            const float wy = wy_l[l];

            float2 A = __ldg((const float2*)(px0 + o0));
            float2 B = __ldg((const float2*)(px0 + o1));
            float P2 = fmaf(wy, B.x - A.x, A.x);
            float P3 = fmaf(wy, B.y - A.y, A.y);

            float hP0 = 0.f, hP1 = 0.f;
            if (edge) {
                float a0 = __ldg(basec + o0 + h0), b0 = __ldg(basec + o1 + h0);
                float a1 = __ldg(basec + o0 + h1), b1 = __ldg(basec + o1 + h1);
                hP0 = fmaf(wy, b0 - a0, a0);
                hP1 = fmaf(wy, b1 - a1, a1);
            }

            float Pm1 = __shfl_up_sync(0xffffffffu, P3, 1);
            float Pm2 = __shfl_up_sync(0xffffffffu, P2, 1);
            float Pp2 = __shfl_down_sync(0xffffffffu, P2, 1);
            float Pp3 = __shfl_down_sync(0xffffffffu, P3, 1);
            if (isL) { Pm2 = hP0; Pm1 = hP1; }
            if (isR) { Pp2 = hP0; Pp3 = hP1; }

            float D1 = P2  - Pm1;
            float D2 = P3  - P2;
            float D3 = Pp2 - P3;

            float va[7], vb[7];
            if (!armB[l]) {
                va[0] = fmaf(u0[l], D2, P2);
                va[1] = fmaf(u1[l], D2, P2);
                va[2] = fmaf(u2[l], D2, P2);
                va[3] = P2;
                va[4] = fmaf(u4[l], D1, Pm1);
                va[5] = fmaf(u5[l], D1, Pm1);
                va[6] = fmaf(u6[l], D1, Pm1);
                vb[0] = fmaf(u0[l], D3, P3);
                vb[1] = fmaf(u1[l], D3, P3);
                vb[2] = fmaf(u2[l], D3, P3);
                vb[3] = P3;
                vb[4] = fmaf(u4[l], D2, P2);
                vb[5] = fmaf(u5[l], D2, P2);
                vb[6] = fmaf(u6[l], D2, P2);
            } else {
                float D0 = Pm1 - Pm2;
                float D4 = Pp3 - Pp2;
                va[0] = fmaf(u0[l], D3, P3);
                va[1] = fmaf(u1[l], D2, P2);
                va[2] = fmaf(u2[l], D2, P2);
                va[3] = P2;
                va[4] = fmaf(u4[l], D1, Pm1);
                va[5] = fmaf(u5[l], D1, Pm1);
                va[6] = fmaf(u6[l], D0, Pm2);
                vb[0] = fmaf(u0[l], D4, Pp2);
                vb[1] = fmaf(u1[l], D3, P3);
                vb[2] = fmaf(u2[l], D3, P3);
                vb[3] = P3;
                vb[4] = fmaf(u4[l], D2, P2);
                vb[5] = fmaf(u5[l], D2, P2);
                vb[6] = fmaf(u6[l], D1, Pm1);
            }

            if (l == 0) {
#pragma unroll
                for (int i = 0; i < 7; i++) { p0[i] = va[i]; p1[i] = vb[i]; }
            } else if (l == 1) {
#pragma unroll
                for (int i = 0; i < 7; i++) { p0[i] *= va[i]; p1[i] *= vb[i]; }
            } else {
#pragma unroll
                for (int i = 0; i < 7; i++) {
                    sum0[i] = fmaf(p0[i], va[i], sum0[i]);
                    sum1[i] = fmaf(p1[i], vb[i], sum1[i]);
                }
            }
        }
    }

    // write (N, A2, C, H, W); a = kq*7 + lq ; pixel pair -> STG.64
    float* o = out + ((size_t)((n * 49 + kq * 7) * 3 + c)) * HWD + y * Wd + x;
#pragma unroll
    for (int lq = 0; lq < 7; lq++) {
        float2 v = make_float2(sum0[lq] * 0.25f, sum1[lq] * 0.25f);
        *(float2*)(o + (size_t)lq * 3 * HWD) = v;
    }
}

extern "C" void kernel_launch(void* const* d_in, const int* in_sizes, int n_in,
                              void* d_out, int out_size)
{
    const float* low_rank = (const float*)d_in[0];
    const float* planes   = (const float*)d_in[1];
    float* out = (float*)d_out;

    dim3 block(32, 8, 1);
    dim3 grid(Wd / 64, Hd / 8, 42);   // z = n*21 + kq*3 + c, N=2
    lfs2_kernel<<<grid, block>>>(low_rank, planes, out);
}

// round 8
// speedup vs baseline: 1.7386x; 1.7386x over previous
#include <cuda_runtime.h>

#define Wd 384
#define Hd 256
#define HWD (Wd*Hd)

// Output: (N=2, A2=49, C=3, H, W) fp32
// Input0: low_rank (N, L=3, R=4, C=3, H, W) fp32 ; Input1: planes (N, L)
//
// Identity grid + constant per-(n,l,view) shift; taps/weights pixel-independent;
// borders via clamped load addresses. Lane owns pixels (x, x+1); neighbor
// column interps via __shfl (3x load dedup); lanes 0/31 load clamped halo pairs.
// All loads for one rank-iteration are batched upfront (MLP ~ 6-18); view
// weights rematerialized per slice (6 FMA) instead of stored (reg pressure).

__global__ __launch_bounds__(256, 3)
void lfs3_kernel(const float* __restrict__ lr,
                 const float* __restrict__ planes,
                 float* __restrict__ out)
{
    const int lane = threadIdx.x;
    const int XB = blockIdx.x * 64;
    const int x  = XB + lane * 2;
    const int y  = blockIdx.y * 8 + threadIdx.y;
    const int z  = blockIdx.z;                 // n*21 + kq*3 + c
    const int n  = z / 21;
    const int zc = z - n * 21;
    const int kq = zc / 3;
    const int c  = zc - kq * 3;

    const float cy = 255.0f / 512.0f;
    const float cx = 383.0f / 768.0f;

    const bool isL = (lane == 0), isR = (lane == 31);
    const bool edge = isL || isR;
    const int h0 = isR ? min(x + 2, Wd - 1) : max(x - 2, 0);
    const int h1 = isR ? min(x + 3, Wd - 1) : max(x - 1, 0);

    const float* basec = lr + (size_t)(n * 36 + c) * HWD;

    float wy_l[3], s_l[3], a0_l[3], a6_l[3];
    int lo_l[3], hi_l[3];
#pragma unroll
    for (int l = 0; l < 3; l++) {
        float p   = __ldg(planes + n * 3 + l);
        float dyv = p * cy * (float)(3 - kq);
        float fy  = floorf(dyv);
        wy_l[l]   = dyv - fy;
        int iy0   = y + (int)fy;
        lo_l[l] = l * (12 * HWD) + min(max(iy0,     0), Hd - 1) * Wd;
        hi_l[l] = l * (12 * HWD) + min(max(iy0 + 1, 0), Hd - 1) * Wd;
        float s = p * cx;
        s_l[l]  = s;
        bool b  = (3.0f * s > 1.0f);
        a0_l[l] = b ? -1.0f : 0.0f;   // w0 = 3s + a0
        a6_l[l] = b ?  2.0f : 1.0f;   // w6 = a6 - 3s
    }

    float sum0[7], sum1[7];
#pragma unroll
    for (int i = 0; i < 7; i++) { sum0[i] = 0.0f; sum1[i] = 0.0f; }

    int roff = 0;
#pragma unroll 1
    for (int r = 0; r < 4; r++, roff += 3 * HWD) {
        // ---- upfront batched loads (own pairs, all layers; halo for edge lanes)
        float2 A[3], B[3];
#pragma unroll
        for (int l = 0; l < 3; l++) {
            A[l] = __ldg((const float2*)(basec + (roff + lo_l[l] + x)));
            B[l] = __ldg((const float2*)(basec + (roff + hi_l[l] + x)));
        }
        float ha0[3], ha1[3], hb0[3], hb1[3];
        if (edge) {
#pragma unroll
            for (int l = 0; l < 3; l++) {
                ha0[l] = __ldg(basec + (roff + lo_l[l] + h0));
                ha1[l] = __ldg(basec + (roff + lo_l[l] + h1));
                hb0[l] = __ldg(basec + (roff + hi_l[l] + h0));
                hb1[l] = __ldg(basec + (roff + hi_l[l] + h1));
            }
        }

        float p0[7], p1[7];
#pragma unroll
        for (int l = 0; l < 3; l++) {
            const float wy = wy_l[l];
            const float s  = s_l[l];
            const bool armB = (a0_l[l] != 0.0f);

            float P2 = fmaf(wy, B[l].x - A[l].x, A[l].x);
            float P3 = fmaf(wy, B[l].y - A[l].y, A[l].y);

            float Pm1 = __shfl_up_sync(0xffffffffu, P3, 1);
            float Pm2 = __shfl_up_sync(0xffffffffu, P2, 1);
            float Pp2 = __shfl_down_sync(0xffffffffu, P2, 1);
            float Pp3 = __shfl_down_sync(0xffffffffu, P3, 1);
            if (edge) {
                float hP0 = fmaf(wy, hb0[l] - ha0[l], ha0[l]);
                float hP1 = fmaf(wy, hb1[l] - ha1[l], ha1[l]);
                if (isL) { Pm2 = hP0; Pm1 = hP1; }
                else     { Pp2 = hP0; Pp3 = hP1; }
            }

            // weights (rematerialized, 6 fma-pipe ops)
            const float w0 = fmaf(3.0f, s, a0_l[l]);
            const float w1 = 2.0f * s;
            const float w2 = s;
            const float w4 = 1.0f - s;
            const float w5 = fmaf(-2.0f, s, 1.0f);
            const float w6 = fmaf(-3.0f, s, a6_l[l]);

            float D1 = P2  - Pm1;
            float D2 = P3  - P2;
            float D3 = Pp2 - P3;

            float va[7], vb[7];
            if (!armB) {
                va[0] = fmaf(w0, D2, P2);
                va[1] = fmaf(w1, D2, P2);
                va[2] = fmaf(w2, D2, P2);
                va[3] = P2;
                va[4] = fmaf(w4, D1, Pm1);
                va[5] = fmaf(w5, D1, Pm1);
                va[6] = fmaf(w6, D1, Pm1);
                vb[0] = fmaf(w0, D3, P3);
                vb[1] = fmaf(w1, D3, P3);
                vb[2] = fmaf(w2, D3, P3);
                vb[3] = P3;
                vb[4] = fmaf(w4, D2, P2);
                vb[5] = fmaf(w5, D2, P2);
                vb[6] = fmaf(w6, D2, P2);
            } else {
                float D0 = Pm1 - Pm2;
                float D4 = Pp3 - Pp2;
                va[0] = fmaf(w0, D3, P3);
                va[1] = fmaf(w1, D2, P2);
                va[2] = fmaf(w2, D2, P2);
                va[3] = P2;
                va[4] = fmaf(w4, D1, Pm1);
                va[5] = fmaf(w5, D1, Pm1);
                va[6] = fmaf(w6, D0, Pm2);
                vb[0] = fmaf(w0, D4, Pp2);
                vb[1] = fmaf(w1, D3, P3);
                vb[2] = fmaf(w2, D3, P3);
                vb[3] = P3;
                vb[4] = fmaf(w4, D2, P2);
                vb[5] = fmaf(w5, D2, P2);
                vb[6] = fmaf(w6, D1, Pm1);
            }

            if (l == 0) {
#pragma unroll
                for (int i = 0; i < 7; i++) { p0[i] = va[i]; p1[i] = vb[i]; }
            } else if (l == 1) {
#pragma unroll
                for (int i = 0; i < 7; i++) { p0[i] *= va[i]; p1[i] *= vb[i]; }
            } else {
#pragma unroll
                for (int i = 0; i < 7; i++) {
                    sum0[i] = fmaf(p0[i], va[i], sum0[i]);
                    sum1[i] = fmaf(p1[i], vb[i], sum1[i]);
                }
            }
        }
    }

    // write (N, A2, C, H, W); a = kq*7 + lq ; pixel pair -> STG.64
    float* o = out + ((size_t)((n * 49 + kq * 7) * 3 + c)) * HWD + y * Wd + x;
#pragma unroll
    for (int lq = 0; lq < 7; lq++) {
        float2 v = make_float2(sum0[lq] * 0.25f, sum1[lq] * 0.25f);
        *(float2*)(o + (size_t)lq * 3 * HWD) = v;
    }
}

extern "C" void kernel_launch(void* const* d_in, const int* in_sizes, int n_in,
                              void* d_out, int out_size)
{
    const float* low_rank = (const float*)d_in[0];
    const float* planes   = (const float*)d_in[1];
    float* out = (float*)d_out;

    dim3 block(32, 8, 1);
    dim3 grid(Wd / 64, Hd / 8, 42);   // z = n*21 + kq*3 + c, N=2
    lfs3_kernel<<<grid, block>>>(low_rank, planes, out);
}

// round 9
// speedup vs baseline: 2.1977x; 1.2641x over previous
#include <cuda_runtime.h>

#define Wd 384
#define Hd 256
#define HWD (Wd*Hd)

// Output: (N=2, A2=49, C=3, H, W) fp32
// Input0: low_rank (N, L=3, R=4, C=3, H, W) fp32 ; Input1: planes (N, L)
//
// Identity grid + constant per-(n,l,view) shift; taps/weights pixel-independent;
// borders via clamped load addresses. Lane owns 4 pixels (x..x+3) loaded as
// float4; neighbor column interps via __shfl; lanes 0/31 load clamped halo.
// Extended column array E[0..7] = cols x-2 .. x+5 (pattern A uses E[1..6]).

__global__ __launch_bounds__(256, 2)
void lf4px_kernel(const float* __restrict__ lr,
                  const float* __restrict__ planes,
                  float* __restrict__ out)
{
    const int lane = threadIdx.x;
    const int XB = blockIdx.x * 128;
    const int x  = XB + lane * 4;
    const int y  = blockIdx.y * 8 + threadIdx.y;
    const int z  = blockIdx.z;                 // n*21 + kq*3 + c
    const int n  = z / 21;
    const int zc = z - n * 21;
    const int kq = zc / 3;
    const int c  = zc - kq * 3;

    const float cy = 255.0f / 512.0f;
    const float cx = 383.0f / 768.0f;

    const bool isL = (lane == 0), isR = (lane == 31);
    const bool edge = isL || isR;
    const int h0 = isR ? min(x + 4, Wd - 1) : max(x - 2, 0);
    const int h1 = isR ? min(x + 5, Wd - 1) : max(x - 1, 0);

    const float* basec = lr + (size_t)(n * 36 + c) * HWD;

    float wy_l[3], s_l[3], a0_l[3], a6_l[3];
    int lo_l[3], hi_l[3];
#pragma unroll
    for (int l = 0; l < 3; l++) {
        float p   = __ldg(planes + n * 3 + l);
        float dyv = p * cy * (float)(3 - kq);
        float fy  = floorf(dyv);
        wy_l[l]   = dyv - fy;
        int iy0   = y + (int)fy;
        lo_l[l] = l * (12 * HWD) + min(max(iy0,     0), Hd - 1) * Wd;
        hi_l[l] = l * (12 * HWD) + min(max(iy0 + 1, 0), Hd - 1) * Wd;
        float s = p * cx;
        s_l[l]  = s;
        bool b  = (3.0f * s > 1.0f);
        a0_l[l] = b ? -1.0f : 0.0f;   // w0 = 3s + a0
        a6_l[l] = b ?  2.0f : 1.0f;   // w6 = a6 - 3s
    }

    float sum[4][7];
#pragma unroll
    for (int p = 0; p < 4; p++)
#pragma unroll
        for (int v = 0; v < 7; v++) sum[p][v] = 0.0f;

    int roff = 0;
#pragma unroll 1
    for (int r = 0; r < 4; r++, roff += 3 * HWD) {
        // upfront batched loads: own float4 pairs (all layers) + edge halo
        float4 A[3], B[3];
#pragma unroll
        for (int l = 0; l < 3; l++) {
            A[l] = __ldg((const float4*)(basec + (roff + lo_l[l] + x)));
            B[l] = __ldg((const float4*)(basec + (roff + hi_l[l] + x)));
        }
        float ha0[3], ha1[3], hb0[3], hb1[3];
        if (edge) {
#pragma unroll
            for (int l = 0; l < 3; l++) {
                ha0[l] = __ldg(basec + (roff + lo_l[l] + h0));
                ha1[l] = __ldg(basec + (roff + lo_l[l] + h1));
                hb0[l] = __ldg(basec + (roff + hi_l[l] + h0));
                hb1[l] = __ldg(basec + (roff + hi_l[l] + h1));
            }
        }

        float prod[4][7];
#pragma unroll
        for (int l = 0; l < 3; l++) {
            const float wy = wy_l[l];
            const float s  = s_l[l];
            const bool armB = (a0_l[l] != 0.0f);

            // weights (rematerialized)
            const float w0 = fmaf(3.0f, s, a0_l[l]);
            const float w1 = 2.0f * s;
            const float w2 = s;
            const float w4 = 1.0f - s;
            const float w5 = fmaf(-2.0f, s, 1.0f);
            const float w6 = fmaf(-3.0f, s, a6_l[l]);

            // own column interps: E[2..5] = cols x..x+3
            float E2 = fmaf(wy, B[l].x - A[l].x, A[l].x);
            float E3 = fmaf(wy, B[l].y - A[l].y, A[l].y);
            float E4 = fmaf(wy, B[l].z - A[l].z, A[l].z);
            float E5 = fmaf(wy, B[l].w - A[l].w, A[l].w);

            float hP0 = 0.f, hP1 = 0.f;
            if (edge) {
                hP0 = fmaf(wy, hb0[l] - ha0[l], ha0[l]);
                hP1 = fmaf(wy, hb1[l] - ha1[l], ha1[l]);
            }

            if (!armB) {
                // needs cols x-1 .. x+4 : E[1..6]
                float E1 = __shfl_up_sync(0xffffffffu, E5, 1);    // col x-1
                float E6 = __shfl_down_sync(0xffffffffu, E2, 1);  // col x+4
                if (isL) E1 = hP1;
                if (isR) E6 = hP0;
                float Ea[6] = {E1, E2, E3, E4, E5, E6};   // cols x-1..x+4
                float Da[5];
#pragma unroll
                for (int j = 0; j < 5; j++) Da[j] = Ea[j + 1] - Ea[j];
                // pixel p: base idx p+1 in Ea (col x+p); left base p (col x+p-1)
#pragma unroll
                for (int p = 0; p < 4; p++) {
                    float Pb = Ea[p + 1], Db = Da[p + 1];
                    float Pl = Ea[p],     Dl = Da[p];
                    float va[7];
                    va[0] = fmaf(w0, Db, Pb);
                    va[1] = fmaf(w1, Db, Pb);
                    va[2] = fmaf(w2, Db, Pb);
                    va[3] = Pb;
                    va[4] = fmaf(w4, Dl, Pl);
                    va[5] = fmaf(w5, Dl, Pl);
                    va[6] = fmaf(w6, Dl, Pl);
                    if (l == 0) {
#pragma unroll
                        for (int v = 0; v < 7; v++) prod[p][v] = va[v];
                    } else if (l == 1) {
#pragma unroll
                        for (int v = 0; v < 7; v++) prod[p][v] *= va[v];
                    } else {
#pragma unroll
                        for (int v = 0; v < 7; v++)
                            sum[p][v] = fmaf(prod[p][v], va[v], sum[p][v]);
                    }
                }
            } else {
                // needs cols x-2 .. x+5 : E[0..7]
                float E1 = __shfl_up_sync(0xffffffffu, E5, 1);    // col x-1
                float E0 = __shfl_up_sync(0xffffffffu, E4, 1);    // col x-2
                float E6 = __shfl_down_sync(0xffffffffu, E2, 1);  // col x+4
                float E7 = __shfl_down_sync(0xffffffffu, E3, 1);  // col x+5
                if (isL) { E0 = hP0; E1 = hP1; }
                if (isR) { E6 = hP0; E7 = hP1; }
                float Eb[8] = {E0, E1, E2, E3, E4, E5, E6, E7};   // cols x-2..x+5
                float Db[7];
#pragma unroll
                for (int j = 0; j < 7; j++) Db[j] = Eb[j + 1] - Eb[j];
                // pixel p: col x+p is Eb[p+2]
#pragma unroll
                for (int p = 0; p < 4; p++) {
                    float va[7];
                    va[0] = fmaf(w0, Db[p + 3], Eb[p + 3]);
                    va[1] = fmaf(w1, Db[p + 2], Eb[p + 2]);
                    va[2] = fmaf(w2, Db[p + 2], Eb[p + 2]);
                    va[3] = Eb[p + 2];
                    va[4] = fmaf(w4, Db[p + 1], Eb[p + 1]);
                    va[5] = fmaf(w5, Db[p + 1], Eb[p + 1]);
                    va[6] = fmaf(w6, Db[p],     Eb[p]);
                    if (l == 0) {
#pragma unroll
                        for (int v = 0; v < 7; v++) prod[p][v] = va[v];
                    } else if (l == 1) {
#pragma unroll
                        for (int v = 0; v < 7; v++) prod[p][v] *= va[v];
                    } else {
#pragma unroll
                        for (int v = 0; v < 7; v++)
                            sum[p][v] = fmaf(prod[p][v], va[v], sum[p][v]);
                    }
                }
            }
        }
    }

    // write (N, A2, C, H, W); a = kq*7 + lq ; 4 pixels -> STG.128
    float* o = out + ((size_t)((n * 49 + kq * 7) * 3 + c)) * HWD + y * Wd + x;
#pragma unroll
    for (int lq = 0; lq < 7; lq++) {
        float4 v = make_float4(sum[0][lq] * 0.25f, sum[1][lq] * 0.25f,
                               sum[2][lq] * 0.25f, sum[3][lq] * 0.25f);
        *(float4*)(o + (size_t)lq * 3 * HWD) = v;
    }
}

extern "C" void kernel_launch(void* const* d_in, const int* in_sizes, int n_in,
                              void* d_out, int out_size)
{
    const float* low_rank = (const float*)d_in[0];
    const float* planes   = (const float*)d_in[1];
    float* out = (float*)d_out;

    dim3 block(32, 8, 1);
    dim3 grid(Wd / 128, Hd / 8, 42);   // z = n*21 + kq*3 + c, N=2
    lf4px_kernel<<<grid, block>>>(low_rank, planes, out);
}